// round 2
// baseline (speedup 1.0000x reference)
#include <cuda_runtime.h>
#include <cuda_bf16.h>

// ---------------------------------------------------------------------------
// GAT layer: N=4096, F_IN=512, HID=64, H=8, alpha=0.2
// out[n, h*64+d] = elu( sum_j att[h,n,j] * Wh[h,j,d] )
// att = masked softmax over j of leakyrelu(s[h,n] + d[h,j])
// Key trick: exp(leakyrelu(s+d)) factorizes:
//   t>0 : exp(s)*exp(d)      t<=0 : exp(0.2s)*exp(0.2d)
// so softmax needs no per-edge exp, and adj sparsity (1%) makes the
// aggregation a ~42-neighbor gather instead of a dense 4096 matvec.
// ---------------------------------------------------------------------------

#define N_NODES 4096
#define F_IN    512
#define HID     64
#define NHEADS  8
#define NCOLS   (NHEADS * HID)   // 512

// scratch (static device allocations only — no cudaMalloc allowed)
__device__ float  g_Wh[N_NODES * NCOLS];        // [N][H*64] = 8 MB
__device__ float4 g_SAB[NHEADS * N_NODES];      // (s, exp(s), exp(0.2s), 0)
__device__ float4 g_DJE[NHEADS * N_NODES];      // (d, exp(d), exp(0.2d), 0)

// ---------------------------------------------------------------------------
// Kernel 1: Wh = x @ Wcat.  Block tile 128x64, BK=32, 256 threads, 8x4/thread.
// blockIdx.x = head (the 64-col tile is exactly one head -> contiguous W load)
// ---------------------------------------------------------------------------
#define BM 128
#define BN 64
#define BK 32

__global__ __launch_bounds__(256) void gemm_kernel(const float* __restrict__ x,
                                                   const float* __restrict__ W)
{
    __shared__ float AsT[BK][BM + 4];   // [k][m], padded
    __shared__ float Bs[BK][BN];        // [k][n]

    const int tid = threadIdx.x;
    const int m0  = blockIdx.y * BM;
    const int h   = blockIdx.x;
    const float* Whead = W + (size_t)h * F_IN * HID;  // W[h][k][d]

    const int ty = tid >> 4;   // 0..15
    const int tx = tid & 15;   // 0..15

    float acc[8][4];
#pragma unroll
    for (int r = 0; r < 8; r++)
#pragma unroll
        for (int c = 0; c < 4; c++) acc[r][c] = 0.f;

    for (int k0 = 0; k0 < F_IN; k0 += BK) {
        // A tile: 128 rows x 32 cols = 1024 float4, 4 per thread
#pragma unroll
        for (int p = 0; p < 4; p++) {
            int id = tid + p * 256;
            int ar = id >> 3;          // 0..127
            int ac = (id & 7) * 4;     // 0..28
            float4 v = *(const float4*)(x + (size_t)(m0 + ar) * F_IN + k0 + ac);
            AsT[ac + 0][ar] = v.x;
            AsT[ac + 1][ar] = v.y;
            AsT[ac + 2][ar] = v.z;
            AsT[ac + 3][ar] = v.w;
        }
        // B tile: 32 rows x 64 cols = 512 float4, 2 per thread (contiguous)
#pragma unroll
        for (int p = 0; p < 2; p++) {
            int id = tid + p * 256;
            int br = id >> 4;          // 0..31
            int bc = (id & 15) * 4;    // 0..60
            *(float4*)&Bs[br][bc] =
                *(const float4*)(Whead + (size_t)(k0 + br) * HID + bc);
        }
        __syncthreads();

#pragma unroll
        for (int k = 0; k < BK; k++) {
            float a_frag[8];
#pragma unroll
            for (int r = 0; r < 8; r++) a_frag[r] = AsT[k][ty * 8 + r];
            float4 b4 = *(float4*)&Bs[k][tx * 4];
            float b_frag[4] = {b4.x, b4.y, b4.z, b4.w};
#pragma unroll
            for (int r = 0; r < 8; r++)
#pragma unroll
                for (int c = 0; c < 4; c++)
                    acc[r][c] = fmaf(a_frag[r], b_frag[c], acc[r][c]);
        }
        __syncthreads();
    }

#pragma unroll
    for (int r = 0; r < 8; r++) {
        float4 v = make_float4(acc[r][0], acc[r][1], acc[r][2], acc[r][3]);
        *(float4*)(g_Wh + (size_t)(m0 + ty * 8 + r) * NCOLS + h * HID + tx * 4) = v;
    }
}

// ---------------------------------------------------------------------------
// Kernel 2: per (i,h): s = a[h,:64].Wh_row, d = a[h,64:].Wh_row, plus exps.
// One warp per (i,h). grid = 4096 blocks x 8 warps.
// ---------------------------------------------------------------------------
__global__ __launch_bounds__(256) void sd_kernel(const float* __restrict__ a)
{
    const int i    = blockIdx.x;
    const int h    = threadIdx.x >> 5;
    const int lane = threadIdx.x & 31;

    const float* row = g_Wh + (size_t)i * NCOLS + h * HID;
    const float* ah  = a + h * (2 * HID);

    float v0 = row[lane], v1 = row[lane + 32];
    float s = v0 * ah[lane]      + v1 * ah[lane + 32];
    float d = v0 * ah[64 + lane] + v1 * ah[96 + lane];
#pragma unroll
    for (int o = 16; o; o >>= 1) {
        s += __shfl_xor_sync(0xffffffffu, s, o);
        d += __shfl_xor_sync(0xffffffffu, d, o);
    }
    if (lane == 0) {
        g_SAB[h * N_NODES + i] = make_float4(s, expf(s), expf(0.2f * s), 0.f);
        g_DJE[h * N_NODES + i] = make_float4(d, expf(d), expf(0.2f * d), 0.f);
    }
}

// ---------------------------------------------------------------------------
// Kernel 3: one block per destination row i, 512 threads = (h, d).
// Phase 1: deterministic ballot-scan of adj row -> shared neighbor list.
// Phase 2: per 64-neighbor chunk, stage w[h][k] in smem, then every thread
//          accumulates acc += w * Wh[j, tid] and den += w (identical per head).
// ---------------------------------------------------------------------------
__global__ __launch_bounds__(512) void attn_kernel(const float* __restrict__ adj,
                                                   float* __restrict__ out)
{
    __shared__ int   s_list[N_NODES];   // worst-case capacity
    __shared__ float s_w[NHEADS][64];
    __shared__ int   s_warpcnt[16];
    __shared__ int   s_cnt;

    const int i    = blockIdx.x;
    const int tid  = threadIdx.x;
    const int lane = tid & 31;
    const int wid  = tid >> 5;
    const int h    = tid >> 6;     // 0..7
    const int kk   = tid & 63;     // column within head / chunk slot

    if (tid == 0) s_cnt = 0;
    __syncthreads();

    // ---- Phase 1: build neighbor list (deterministic ascending order) ----
    const float* arow = adj + (size_t)i * N_NODES;
    for (int b = 0; b < N_NODES; b += 512) {
        bool p = (arow[b + tid] > 0.f);
        unsigned mask = __ballot_sync(0xffffffffu, p);
        if (lane == 0) s_warpcnt[wid] = __popc(mask);
        __syncthreads();
        int pre = s_cnt;
#pragma unroll
        for (int w2 = 0; w2 < 16; ++w2)
            if (w2 < wid) pre += s_warpcnt[w2];
        if (p) s_list[pre + __popc(mask & ((1u << lane) - 1u))] = b + tid;
        __syncthreads();
        if (tid == 0) {
            int t = 0;
#pragma unroll
            for (int w2 = 0; w2 < 16; ++w2) t += s_warpcnt[w2];
            s_cnt += t;
        }
        __syncthreads();
    }
    const int nn = s_cnt;

    // ---- Phase 2: weighted aggregation ----
    float4 sab = g_SAB[h * N_NODES + i];
    const float s_i = sab.x, A = sab.y, B = sab.z;

    float acc = 0.f, den = 0.f;

    for (int c = 0; c < nn; c += 64) {
        const int rem = min(64, nn - c);

        // stage edge weights for this chunk: thread (h, kk) -> w for neighbor kk
        float wv = 0.f;
        if (kk < rem) {
            int j = s_list[c + kk];
            float4 dje = g_DJE[h * N_NODES + j];
            float t = s_i + dje.x;
            wv = (t > 0.f) ? A * dje.y : B * dje.z;
        }
        __syncthreads();            // prior chunk's consumers done
        s_w[h][kk] = wv;
        __syncthreads();            // weights visible

        // accumulate: thread (h, dd=kk) over neighbors in chunk
#pragma unroll 4
        for (int q = 0; q < rem; ++q) {
            float wq = s_w[h][q];
            int   j  = s_list[c + q];
            acc = fmaf(wq, g_Wh[((size_t)j << 9) + tid], acc);
            den += wq;
        }
    }

    float r = acc / den;
    out[(size_t)i * NCOLS + tid] = (r > 0.f) ? r : (expf(r) - 1.f);
}

// ---------------------------------------------------------------------------
extern "C" void kernel_launch(void* const* d_in, const int* in_sizes, int n_in,
                              void* d_out, int out_size)
{
    const float* x   = (const float*)d_in[0];   // [4096, 512]
    const float* adj = (const float*)d_in[1];   // [4096, 4096]
    const float* W   = (const float*)d_in[2];   // [8, 512, 64]
    const float* a   = (const float*)d_in[3];   // [8, 128]
    float* out = (float*)d_out;                 // [4096, 512]

    dim3 g1(NHEADS, N_NODES / BM);              // (8, 32)
    gemm_kernel<<<g1, 256>>>(x, W);
    sd_kernel<<<N_NODES, 256>>>(a);
    attn_kernel<<<N_NODES, 512>>>(adj, out);
}

// round 3
// speedup vs baseline: 1.3697x; 1.3697x over previous
#include <cuda_runtime.h>
#include <cuda_bf16.h>
#include <cstdint>

// ---------------------------------------------------------------------------
// GAT layer: N=4096, F_IN=512, HID=64, H=8, alpha=0.2
//   out[n, h*64+d] = elu( softmax_j(leakyrelu(s[h,n]+d[h,j]), mask=adj) @ Wh )
// exp(leakyrelu(s+d)) factorizes -> no per-edge exp.
// adj is 1% dense -> CSR gather instead of dense matvec.
// GEMM on tensor cores (3xTF32 compensated mma.sync) instead of FFMA.
// ---------------------------------------------------------------------------

#define N_NODES 4096
#define F_IN    512
#define HID     64
#define NHEADS  8
#define NCOLS   (NHEADS * HID)   // 512
#define CAP     512              // max neighbors per row (1% density -> ~42 avg)

// static device scratch (no cudaMalloc allowed)
__device__ float  g_Wh[N_NODES * NCOLS];        // [N][H*64] = 8 MB
__device__ float4 g_SAB[NHEADS * N_NODES];      // (s, exp(s), exp(0.2s), 0)
__device__ float4 g_DJE[NHEADS * N_NODES];      // (d, exp(d), exp(0.2d), 0)
__device__ int    g_deg[N_NODES];
__device__ int    g_nbr[N_NODES * CAP];         // 8 MB

// ---------------------------------------------------------------------------
// Kernel 0: adjacency row scan -> CSR (deterministic ascending order).
// 1 block / row, 256 threads, 16 cols per thread (4x float4).
// ---------------------------------------------------------------------------
__global__ __launch_bounds__(256) void scan_kernel(const float* __restrict__ adj)
{
    __shared__ int wsum[8];
    const int i   = blockIdx.x;
    const int tid = threadIdx.x;
    const int lane = tid & 31, wid = tid >> 5;

    const float4* row = (const float4*)(adj + (size_t)i * N_NODES) + tid * 4;
    unsigned bits = 0;
#pragma unroll
    for (int p = 0; p < 4; p++) {
        float4 v = row[p];
        if (v.x > 0.f) bits |= 1u << (p * 4 + 0);
        if (v.y > 0.f) bits |= 1u << (p * 4 + 1);
        if (v.z > 0.f) bits |= 1u << (p * 4 + 2);
        if (v.w > 0.f) bits |= 1u << (p * 4 + 3);
    }
    int cnt = __popc(bits);

    // block exclusive scan
    int incl = cnt;
#pragma unroll
    for (int o = 1; o < 32; o <<= 1) {
        int t = __shfl_up_sync(0xffffffffu, incl, o);
        if (lane >= o) incl += t;
    }
    if (lane == 31) wsum[wid] = incl;
    __syncthreads();
    int wbase = 0;
#pragma unroll
    for (int w = 0; w < 8; w++) if (w < wid) wbase += wsum[w];
    int pos = wbase + incl - cnt;

    if (tid == 0) {
        int t = 0;
#pragma unroll
        for (int w = 0; w < 8; w++) t += wsum[w];
        g_deg[i] = t;
    }

    int base = tid * 16;
    int* dst = g_nbr + (size_t)i * CAP;
    while (bits) {
        int b = __ffs(bits) - 1;
        bits &= bits - 1;
        dst[pos++] = base + b;
    }
}

// ---------------------------------------------------------------------------
// Kernel 1: Wh = x @ W (per head), 3xTF32 tensor-core GEMM.
// Block 128x64 (one head), BK=16, 256 threads, 8 warps in 4(m) x 2(n) grid,
// warp tile 32x32 = 2 m16-tiles x 4 n8-tiles. Smem holds (hi,lo) float2.
// ---------------------------------------------------------------------------
#define GBM 128
#define GBK 16

__device__ __forceinline__ float2 split_tf32(float v)
{
    uint32_t hb, lb;
    asm("cvt.rna.tf32.f32 %0, %1;" : "=r"(hb) : "f"(v));
    float hi = __uint_as_float(hb);
    float lo = v - hi;
    asm("cvt.rna.tf32.f32 %0, %1;" : "=r"(lb) : "f"(lo));
    return make_float2(hi, __uint_as_float(lb));
}

__device__ __forceinline__ void mma_tf32(float* d,
                                         uint32_t a0, uint32_t a1, uint32_t a2, uint32_t a3,
                                         uint32_t b0, uint32_t b1)
{
    asm volatile(
        "mma.sync.aligned.m16n8k8.row.col.f32.tf32.tf32.f32 "
        "{%0,%1,%2,%3}, {%4,%5,%6,%7}, {%8,%9}, {%0,%1,%2,%3};"
        : "+f"(d[0]), "+f"(d[1]), "+f"(d[2]), "+f"(d[3])
        : "r"(a0), "r"(a1), "r"(a2), "r"(a3), "r"(b0), "r"(b1));
}

__global__ __launch_bounds__(256) void gemm_tf32(const float* __restrict__ x,
                                                 const float* __restrict__ W)
{
    __shared__ float2 As[GBM][GBK + 1];   // [m][k] (hi,lo)  128*17*8 = 17.4 KB
    __shared__ float2 Bs[GBK][HID + 1];   // [k][n] (hi,lo)   16*65*8 =  8.3 KB

    const int tid = threadIdx.x;
    const int h   = blockIdx.x;
    const int m0  = blockIdx.y * GBM;
    const float* Whead = W + (size_t)h * F_IN * HID;

    const int warp = tid >> 5, lane = tid & 31;
    const int wm = warp >> 1, wn = warp & 1;
    const int gid = lane >> 2, tig = lane & 3;

    float acc[2][4][4];
#pragma unroll
    for (int mt = 0; mt < 2; mt++)
#pragma unroll
        for (int nt = 0; nt < 4; nt++)
#pragma unroll
            for (int r = 0; r < 4; r++) acc[mt][nt][r] = 0.f;

    // staging coords
    const int ar = tid >> 1;            // 0..127 (A row)
    const int ak = (tid & 1) * 8;       // 0 or 8
    const int br = tid >> 4;            // 0..15  (B row)
    const int bc = (tid & 15) * 4;      // 0..60

    for (int k0 = 0; k0 < F_IN; k0 += GBK) {
        // stage A (with tf32 split)
        {
            const float4* xr = (const float4*)(x + (size_t)(m0 + ar) * F_IN + k0 + ak);
            float4 p = xr[0], q = xr[1];
            float2* d = &As[ar][ak];
            d[0] = split_tf32(p.x); d[1] = split_tf32(p.y);
            d[2] = split_tf32(p.z); d[3] = split_tf32(p.w);
            d[4] = split_tf32(q.x); d[5] = split_tf32(q.y);
            d[6] = split_tf32(q.z); d[7] = split_tf32(q.w);
        }
        // stage B
        {
            float4 w4 = *(const float4*)(Whead + (size_t)(k0 + br) * HID + bc);
            float2* d = &Bs[br][bc];
            d[0] = split_tf32(w4.x); d[1] = split_tf32(w4.y);
            d[2] = split_tf32(w4.z); d[3] = split_tf32(w4.w);
        }
        __syncthreads();

#pragma unroll
        for (int k8 = 0; k8 < 2; k8++) {
            const int kb = k8 * 8;
            // A fragments (2 m16 tiles)
            float2 af[2][4];
#pragma unroll
            for (int mt = 0; mt < 2; mt++) {
                int r0 = wm * 32 + mt * 16 + gid;
                af[mt][0] = As[r0    ][kb + tig];
                af[mt][1] = As[r0 + 8][kb + tig];
                af[mt][2] = As[r0    ][kb + tig + 4];
                af[mt][3] = As[r0 + 8][kb + tig + 4];
            }
            // B fragments (4 n8 tiles)
            float2 bf[4][2];
#pragma unroll
            for (int nt = 0; nt < 4; nt++) {
                int cb = wn * 32 + nt * 8 + gid;
                bf[nt][0] = Bs[kb + tig    ][cb];
                bf[nt][1] = Bs[kb + tig + 4][cb];
            }
#pragma unroll
            for (int mt = 0; mt < 2; mt++) {
                uint32_t ah0 = __float_as_uint(af[mt][0].x), ah1 = __float_as_uint(af[mt][1].x);
                uint32_t ah2 = __float_as_uint(af[mt][2].x), ah3 = __float_as_uint(af[mt][3].x);
                uint32_t al0 = __float_as_uint(af[mt][0].y), al1 = __float_as_uint(af[mt][1].y);
                uint32_t al2 = __float_as_uint(af[mt][2].y), al3 = __float_as_uint(af[mt][3].y);
#pragma unroll
                for (int nt = 0; nt < 4; nt++) {
                    uint32_t bh0 = __float_as_uint(bf[nt][0].x), bh1 = __float_as_uint(bf[nt][1].x);
                    uint32_t bl0 = __float_as_uint(bf[nt][0].y), bl1 = __float_as_uint(bf[nt][1].y);
                    mma_tf32(acc[mt][nt], ah0, ah1, ah2, ah3, bh0, bh1);  // hi*hi
                    mma_tf32(acc[mt][nt], al0, al1, al2, al3, bh0, bh1);  // lo*hi
                    mma_tf32(acc[mt][nt], ah0, ah1, ah2, ah3, bl0, bl1);  // hi*lo
                }
            }
        }
        __syncthreads();
    }

    // epilogue: write [N][H*64]
#pragma unroll
    for (int mt = 0; mt < 2; mt++) {
        int gr = m0 + wm * 32 + mt * 16 + gid;
#pragma unroll
        for (int nt = 0; nt < 4; nt++) {
            int col = h * HID + wn * 32 + nt * 8 + 2 * tig;
            *(float2*)(g_Wh + (size_t)gr * NCOLS + col) =
                make_float2(acc[mt][nt][0], acc[mt][nt][1]);
            *(float2*)(g_Wh + (size_t)(gr + 8) * NCOLS + col) =
                make_float2(acc[mt][nt][2], acc[mt][nt][3]);
        }
    }
}

// ---------------------------------------------------------------------------
// Kernel 2: per (i,h): s = a[h,:64].Wh_row, d = a[h,64:].Wh_row, plus exps.
// ---------------------------------------------------------------------------
__global__ __launch_bounds__(256) void sd_kernel(const float* __restrict__ a)
{
    const int i    = blockIdx.x;
    const int h    = threadIdx.x >> 5;
    const int lane = threadIdx.x & 31;

    const float* row = g_Wh + (size_t)i * NCOLS + h * HID;
    const float* ah  = a + h * (2 * HID);

    float v0 = row[lane], v1 = row[lane + 32];
    float s = v0 * ah[lane]      + v1 * ah[lane + 32];
    float d = v0 * ah[64 + lane] + v1 * ah[96 + lane];
#pragma unroll
    for (int o = 16; o; o >>= 1) {
        s += __shfl_xor_sync(0xffffffffu, s, o);
        d += __shfl_xor_sync(0xffffffffu, d, o);
    }
    if (lane == 0) {
        g_SAB[h * N_NODES + i] = make_float4(s, expf(s), expf(0.2f * s), 0.f);
        g_DJE[h * N_NODES + i] = make_float4(d, expf(d), expf(0.2f * d), 0.f);
    }
}

// ---------------------------------------------------------------------------
// Kernel 3: aggregation. 1 block/row, 512 threads = (head h, dim d).
// ---------------------------------------------------------------------------
__global__ __launch_bounds__(512) void attn_kernel(float* __restrict__ out)
{
    __shared__ int   s_list[CAP];
    __shared__ float s_w[NHEADS][64];

    const int i   = blockIdx.x;
    const int tid = threadIdx.x;
    const int h   = tid >> 6;
    const int kk  = tid & 63;

    const int nn = g_deg[i];
    if (tid < nn) s_list[tid] = g_nbr[(size_t)i * CAP + tid];
    __syncthreads();

    float4 sab = g_SAB[h * N_NODES + i];
    const float s_i = sab.x, A = sab.y, B = sab.z;

    float acc = 0.f, den = 0.f;

    for (int c = 0; c < nn; c += 64) {
        const int rem = min(64, nn - c);

        float wv = 0.f;
        if (kk < rem) {
            int j = s_list[c + kk];
            float4 dje = g_DJE[h * N_NODES + j];
            float t = s_i + dje.x;
            wv = (t > 0.f) ? A * dje.y : B * dje.z;
        }
        if (c) __syncthreads();        // prior chunk's consumers done
        s_w[h][kk] = wv;
        __syncthreads();               // weights visible

#pragma unroll 4
        for (int q = 0; q < rem; ++q) {
            float wq = s_w[h][q];
            int   j  = s_list[c + q];
            acc = fmaf(wq, __ldg(g_Wh + ((size_t)j << 9) + tid), acc);
            den += wq;
        }
    }

    float r = acc / den;
    out[(size_t)i * NCOLS + tid] = (r > 0.f) ? r : (expf(r) - 1.f);
}

// ---------------------------------------------------------------------------
extern "C" void kernel_launch(void* const* d_in, const int* in_sizes, int n_in,
                              void* d_out, int out_size)
{
    const float* x   = (const float*)d_in[0];   // [4096, 512]
    const float* adj = (const float*)d_in[1];   // [4096, 4096]
    const float* W   = (const float*)d_in[2];   // [8, 512, 64]
    const float* a   = (const float*)d_in[3];   // [8, 128]
    float* out = (float*)d_out;                 // [4096, 512]

    scan_kernel<<<N_NODES, 256>>>(adj);
    dim3 g1(NHEADS, N_NODES / GBM);             // (8, 32)
    gemm_tf32<<<g1, 256>>>(x, W);
    sd_kernel<<<N_NODES, 256>>>(a);
    attn_kernel<<<N_NODES, 512>>>(out);
}

// round 8
// speedup vs baseline: 2.5392x; 1.8538x over previous
#include <cuda_runtime.h>
#include <cuda_bf16.h>
#include <cstdint>

// ---------------------------------------------------------------------------
// GAT: N=4096, F_IN=512, HID=64, H=8, alpha=0.2
//  out[n, h*64+d] = elu( softmax_j(leakyrelu(s[h,n]+d[h,j]), mask=adj) @ Wh )
// exp(leakyrelu(s+d)) factorizes -> no per-edge exp.
// adj 1% dense -> CSR gather.
// GEMM: split-bf16 (hi/lo) 3-term compensated mma.sync.m16n8k16 (legacy path;
// tcgen05 PTX features rejected by the harness's compute_103 PTX target).
// ---------------------------------------------------------------------------

#define N_NODES 4096
#define F_IN    512
#define HID     64
#define NHEADS  8
#define NCOLS   512
#define CAP     192            // max degree (binomial mean 41, sd 6.4)

__device__ float          g_Wh[N_NODES * NCOLS];      // [N][H*64]
__device__ float4         g_SAB[N_NODES * NHEADS];    // [i*8+h] = (s, e^s, e^.2s, 0)
__device__ float4         g_DJE[N_NODES * NHEADS];    // [j*8+h]
__device__ int            g_deg[N_NODES];
__device__ int            g_nbr[N_NODES * CAP];
__device__ __nv_bfloat16  g_Wth[NHEADS * HID * F_IN]; // W^T hi: [h][n][k]
__device__ __nv_bfloat16  g_Wtl[NHEADS * HID * F_IN]; // W^T lo

// ---------------------------------------------------------------------------
// Kernel 0: W transpose + bf16 split: g_Wt{h,l}[h][n][k] = split(W[h][k][n])
// ---------------------------------------------------------------------------
__global__ __launch_bounds__(256) void prep_w(const float* __restrict__ W)
{
    int b  = blockIdx.x * 256 + threadIdx.x;   // 0..65535
    int k4 = (b & 127) * 4;
    int n  = (b >> 7) & 63;
    int h  = b >> 13;
    const float* src = W + (size_t)h * 32768 + (size_t)k4 * 64 + n;

    float v[4] = {src[0], src[64], src[128], src[192]};
    __nv_bfloat16 hi[4], lo[4];
#pragma unroll
    for (int j = 0; j < 4; j++) {
        hi[j] = __float2bfloat16_rn(v[j]);
        lo[j] = __float2bfloat16_rn(v[j] - __bfloat162float(hi[j]));
    }
    size_t o = (size_t)h * 32768 + (size_t)n * 512 + k4;
    *(__nv_bfloat162*)(g_Wth + o)     = __nv_bfloat162(hi[0], hi[1]);
    *(__nv_bfloat162*)(g_Wth + o + 2) = __nv_bfloat162(hi[2], hi[3]);
    *(__nv_bfloat162*)(g_Wtl + o)     = __nv_bfloat162(lo[0], lo[1]);
    *(__nv_bfloat162*)(g_Wtl + o + 2) = __nv_bfloat162(lo[2], lo[3]);
}

// ---------------------------------------------------------------------------
// Kernel 1: adjacency row scan -> CSR (deterministic ascending order)
// ---------------------------------------------------------------------------
__global__ __launch_bounds__(256) void scan_kernel(const float* __restrict__ adj)
{
    __shared__ int wsum[8];
    const int i   = blockIdx.x;
    const int tid = threadIdx.x;
    const int lane = tid & 31, wid = tid >> 5;

    const float4* row = (const float4*)(adj + (size_t)i * N_NODES) + tid * 4;
    unsigned bits = 0;
#pragma unroll
    for (int p = 0; p < 4; p++) {
        float4 v = row[p];
        if (v.x > 0.f) bits |= 1u << (p * 4 + 0);
        if (v.y > 0.f) bits |= 1u << (p * 4 + 1);
        if (v.z > 0.f) bits |= 1u << (p * 4 + 2);
        if (v.w > 0.f) bits |= 1u << (p * 4 + 3);
    }
    int cnt = __popc(bits);
    int incl = cnt;
#pragma unroll
    for (int o = 1; o < 32; o <<= 1) {
        int t = __shfl_up_sync(0xffffffffu, incl, o);
        if (lane >= o) incl += t;
    }
    if (lane == 31) wsum[wid] = incl;
    __syncthreads();
    int wbase = 0;
#pragma unroll
    for (int w = 0; w < 8; w++) if (w < wid) wbase += wsum[w];
    int pos = wbase + incl - cnt;
    if (tid == 0) {
        int t = 0;
#pragma unroll
        for (int w = 0; w < 8; w++) t += wsum[w];
        g_deg[i] = t;
    }
    int base = tid * 16;
    int* dst = g_nbr + (size_t)i * CAP;
    while (bits) {
        int b = __ffs(bits) - 1;
        bits &= bits - 1;
        dst[pos++] = base + b;
    }
}

// ---------------------------------------------------------------------------
// Kernel 2: split-bf16 GEMM. Block 64(M)x64(N)=one head, BK=32, 256 threads.
// 8 warps: wm=warp>>1 (4 x m16), wn=warp&1 (2 x n32 = 4 n8 tiles).
// 3 mma terms per k16: hi*hi + lo*hi + hi*lo  (residual ~1e-5 relative).
// Smem row stride 56 elems (112B = 28 words) -> conflict-free frag loads.
// ---------------------------------------------------------------------------
#define GBM 64
#define GBK 32
#define LDP 56

__device__ __forceinline__ void mma_bf16(float* d, uint32_t a0, uint32_t a1,
                                         uint32_t a2, uint32_t a3,
                                         uint32_t b0, uint32_t b1)
{
    asm volatile(
        "mma.sync.aligned.m16n8k16.row.col.f32.bf16.bf16.f32 "
        "{%0,%1,%2,%3}, {%4,%5,%6,%7}, {%8,%9}, {%0,%1,%2,%3};"
        : "+f"(d[0]), "+f"(d[1]), "+f"(d[2]), "+f"(d[3])
        : "r"(a0), "r"(a1), "r"(a2), "r"(a3), "r"(b0), "r"(b1));
}

__global__ __launch_bounds__(256) void gemm_bf16(const float* __restrict__ x)
{
    __shared__ __nv_bfloat16 Ah[GBM][LDP], Al[GBM][LDP];
    __shared__ __nv_bfloat16 Bh[HID][LDP], Bl[HID][LDP];

    const int tid  = threadIdx.x;
    const int lane = tid & 31, warp = tid >> 5;
    const int h    = blockIdx.x;
    const int m0   = blockIdx.y * GBM;
    const int wm   = warp >> 1, wn = warp & 1;
    const int gid  = lane >> 2, tig = lane & 3;

    const float*         xa  = x + (size_t)m0 * F_IN;
    const __nv_bfloat16* wth = g_Wth + (size_t)h * 32768;
    const __nv_bfloat16* wtl = g_Wtl + (size_t)h * 32768;

    float acc[4][4];
#pragma unroll
    for (int nt = 0; nt < 4; nt++)
#pragma unroll
        for (int r = 0; r < 4; r++) acc[nt][r] = 0.f;

    const int srow = tid >> 2;           // 0..63
    const int skq  = (tid & 3) * 8;      // 0,8,16,24

    for (int k0 = 0; k0 < F_IN; k0 += GBK) {
        // ---- stage A: 64 rows x 32 k, fp32 -> (hi, lo) bf16 ----
        {
            const float4* src = (const float4*)(xa + (size_t)srow * F_IN + k0 + skq);
            float4 p = src[0], q = src[1];
            float v[8] = {p.x, p.y, p.z, p.w, q.x, q.y, q.z, q.w};
            __nv_bfloat16 hi[8], lo[8];
#pragma unroll
            for (int j = 0; j < 8; j++) {
                hi[j] = __float2bfloat16_rn(v[j]);
                lo[j] = __float2bfloat16_rn(v[j] - __bfloat162float(hi[j]));
            }
#pragma unroll
            for (int j = 0; j < 4; j++) {
                *(__nv_bfloat162*)&Ah[srow][skq + 2 * j] = __nv_bfloat162(hi[2 * j], hi[2 * j + 1]);
                *(__nv_bfloat162*)&Al[srow][skq + 2 * j] = __nv_bfloat162(lo[2 * j], lo[2 * j + 1]);
            }
            // ---- stage B: 64 n-rows x 32 k, pre-split, uint4 copies ----
            *(uint4*)&Bh[srow][skq] = *(const uint4*)(wth + (size_t)srow * F_IN + k0 + skq);
            *(uint4*)&Bl[srow][skq] = *(const uint4*)(wtl + (size_t)srow * F_IN + k0 + skq);
        }
        __syncthreads();

#pragma unroll
        for (int c = 0; c < 2; c++) {
            const int kb = c * 16;
            const int r0 = wm * 16 + gid;
            uint32_t ah0 = *(const uint32_t*)&Ah[r0    ][kb + 2 * tig];
            uint32_t ah1 = *(const uint32_t*)&Ah[r0 + 8][kb + 2 * tig];
            uint32_t ah2 = *(const uint32_t*)&Ah[r0    ][kb + 2 * tig + 8];
            uint32_t ah3 = *(const uint32_t*)&Ah[r0 + 8][kb + 2 * tig + 8];
            uint32_t al0 = *(const uint32_t*)&Al[r0    ][kb + 2 * tig];
            uint32_t al1 = *(const uint32_t*)&Al[r0 + 8][kb + 2 * tig];
            uint32_t al2 = *(const uint32_t*)&Al[r0    ][kb + 2 * tig + 8];
            uint32_t al3 = *(const uint32_t*)&Al[r0 + 8][kb + 2 * tig + 8];
#pragma unroll
            for (int nt = 0; nt < 4; nt++) {
                const int col = wn * 32 + nt * 8 + gid;
                uint32_t bh0 = *(const uint32_t*)&Bh[col][kb + 2 * tig];
                uint32_t bh1 = *(const uint32_t*)&Bh[col][kb + 2 * tig + 8];
                uint32_t bl0 = *(const uint32_t*)&Bl[col][kb + 2 * tig];
                uint32_t bl1 = *(const uint32_t*)&Bl[col][kb + 2 * tig + 8];
                mma_bf16(acc[nt], ah0, ah1, ah2, ah3, bh0, bh1);  // hi*hi
                mma_bf16(acc[nt], al0, al1, al2, al3, bh0, bh1);  // lo*hi
                mma_bf16(acc[nt], ah0, ah1, ah2, ah3, bl0, bl1);  // hi*lo
            }
        }
        __syncthreads();
    }

    // epilogue: D layout c0,c1 -> row gid, cols 2tig,2tig+1 ; c2,c3 -> row gid+8
    const int gr = m0 + wm * 16 + gid;
#pragma unroll
    for (int nt = 0; nt < 4; nt++) {
        int col = h * HID + wn * 32 + nt * 8 + 2 * tig;
        *(float2*)(g_Wh + (size_t)gr * NCOLS + col)       = make_float2(acc[nt][0], acc[nt][1]);
        *(float2*)(g_Wh + (size_t)(gr + 8) * NCOLS + col) = make_float2(acc[nt][2], acc[nt][3]);
    }
}

// ---------------------------------------------------------------------------
// Kernel 3: per (i,h): s = a[h,:64].Wh_row, d = a[h,64:].Wh_row, + exps.
// ---------------------------------------------------------------------------
__global__ __launch_bounds__(256) void sd_kernel(const float* __restrict__ a)
{
    const int i    = blockIdx.x;
    const int h    = threadIdx.x >> 5;
    const int lane = threadIdx.x & 31;

    const float* row = g_Wh + (size_t)i * NCOLS + h * HID;
    const float* ah  = a + h * (2 * HID);

    float v0 = row[lane], v1 = row[lane + 32];
    float s = v0 * ah[lane]      + v1 * ah[lane + 32];
    float d = v0 * ah[64 + lane] + v1 * ah[96 + lane];
#pragma unroll
    for (int o = 16; o; o >>= 1) {
        s += __shfl_xor_sync(0xffffffffu, s, o);
        d += __shfl_xor_sync(0xffffffffu, d, o);
    }
    if (lane == 0) {
        g_SAB[i * 8 + h] = make_float4(s, expf(s), expf(0.2f * s), 0.f);
        g_DJE[i * 8 + h] = make_float4(d, expf(d), expf(0.2f * d), 0.f);
    }
}

// ---------------------------------------------------------------------------
// Kernel 4: aggregation. 1 block/row, 128 threads, float4 per thread.
// All H x deg edge weights staged once (single barrier), then a pure
// L2-resident float4 gather of Wh rows.
// ---------------------------------------------------------------------------
__global__ __launch_bounds__(128) void attn_kernel(float* __restrict__ out)
{
    __shared__ int    s_list[CAP];
    __shared__ float  s_w[CAP * 8];     // [q*8+h]
    __shared__ float4 s_sab[8];

    const int i   = blockIdx.x;
    const int tid = threadIdx.x;
    const int h   = tid >> 4;           // 16 threads (64 cols) per head

    const int nn = g_deg[i];
    if (tid < 8) s_sab[tid] = g_SAB[i * 8 + tid];
    for (int p = tid; p < nn; p += 128) s_list[p] = g_nbr[(size_t)i * CAP + p];
    __syncthreads();

    for (int idx = tid; idx < nn * 8; idx += 128) {
        int q = idx >> 3, hh = idx & 7;
        int j = s_list[q];
        float4 dje = g_DJE[j * 8 + hh];
        float4 sab = s_sab[hh];
        float t = sab.x + dje.x;
        s_w[idx] = (t > 0.f) ? sab.y * dje.y : sab.z * dje.z;
    }
    __syncthreads();

    const float4* wh4 = (const float4*)g_Wh;
    const float*  wp  = s_w + h;
    float4 acc = make_float4(0.f, 0.f, 0.f, 0.f);
    float  den = 0.f;

#pragma unroll 4
    for (int q = 0; q < nn; q++) {
        float w = wp[q * 8];
        int   j = s_list[q];
        float4 v = __ldg(&wh4[(size_t)j * 128 + tid]);
        acc.x = fmaf(w, v.x, acc.x);
        acc.y = fmaf(w, v.y, acc.y);
        acc.z = fmaf(w, v.z, acc.z);
        acc.w = fmaf(w, v.w, acc.w);
        den += w;
    }

    float inv = 1.f / den;
    float4 r = make_float4(acc.x * inv, acc.y * inv, acc.z * inv, acc.w * inv);
    r.x = (r.x > 0.f) ? r.x : (expf(r.x) - 1.f);
    r.y = (r.y > 0.f) ? r.y : (expf(r.y) - 1.f);
    r.z = (r.z > 0.f) ? r.z : (expf(r.z) - 1.f);
    r.w = (r.w > 0.f) ? r.w : (expf(r.w) - 1.f);
    *(float4*)(out + (size_t)i * NCOLS + tid * 4) = r;
}

// ---------------------------------------------------------------------------
extern "C" void kernel_launch(void* const* d_in, const int* in_sizes, int n_in,
                              void* d_out, int out_size)
{
    const float* x   = (const float*)d_in[0];   // [4096, 512]
    const float* adj = (const float*)d_in[1];   // [4096, 4096]
    const float* W   = (const float*)d_in[2];   // [8, 512, 64]
    const float* a   = (const float*)d_in[3];   // [8, 128]
    float* out = (float*)d_out;                 // [4096, 512]

    prep_w<<<256, 256>>>(W);
    scan_kernel<<<N_NODES, 256>>>(adj);
    gemm_bf16<<<dim3(NHEADS, N_NODES / GBM), 256>>>(x);
    sd_kernel<<<N_NODES, 256>>>(a);
    attn_kernel<<<N_NODES, 128>>>(out);
}

// round 9
// speedup vs baseline: 3.3001x; 1.2997x over previous
#include <cuda_runtime.h>
#include <cuda_fp16.h>
#include <cstdint>

// ---------------------------------------------------------------------------
// GAT: N=4096, F_IN=512, HID=64, H=8, alpha=0.2
//  out[n, h*64+d] = elu( softmax_j(leakyrelu(s[h,n]+d[h,j]), mask=adj) @ Wh )
// exp(leakyrelu(s+d)) factorizes -> no per-edge exp.  adj 1% dense -> CSR.
// GEMM: split-fp16 2-term (Ah+Al)*Bh via mma.sync.m16n8k16.f16, cp.async
// double-buffered; s/d logits fused into the GEMM epilogue.
// ---------------------------------------------------------------------------

#define N_NODES 4096
#define F_IN    512
#define HID     64
#define NHEADS  8
#define NCOLS   512
#define CAP     192

__device__ float   g_Wh[N_NODES * NCOLS];      // [N][H*64]
__device__ float4  g_SAB[N_NODES * NHEADS];    // [i*8+h] = (s, e^s, e^.2s, 0)
__device__ float4  g_DJE[N_NODES * NHEADS];
__device__ int     g_deg[N_NODES];
__device__ int     g_nbr[N_NODES * CAP];
__device__ __half  g_xh[N_NODES * F_IN];       // x split hi (fp16)
__device__ __half  g_xl[N_NODES * F_IN];       // x split lo
__device__ __half  g_Wth[NHEADS * HID * F_IN]; // W^T fp16: [h][n][k]

// ---------------------------------------------------------------------------
// Kernel 0a: split x -> (hi, lo) fp16
// ---------------------------------------------------------------------------
__global__ __launch_bounds__(256) void prep_x(const float* __restrict__ x)
{
    size_t base = ((size_t)blockIdx.x * 256 + threadIdx.x) * 8;
    float4 p = *(const float4*)(x + base);
    float4 q = *(const float4*)(x + base + 4);
    float v[8] = {p.x, p.y, p.z, p.w, q.x, q.y, q.z, q.w};
    __align__(16) __half hs[8], ls[8];
#pragma unroll
    for (int j = 0; j < 8; j++) {
        hs[j] = __float2half_rn(v[j]);
        ls[j] = __float2half_rn(v[j] - __half2float(hs[j]));
    }
    *(uint4*)(g_xh + base) = *(uint4*)hs;
    *(uint4*)(g_xl + base) = *(uint4*)ls;
}

// ---------------------------------------------------------------------------
// Kernel 0b: W transpose -> fp16: g_Wth[h][n][k] = fp16(W[h][k][n])
// ---------------------------------------------------------------------------
__global__ __launch_bounds__(256) void prep_w(const float* __restrict__ W)
{
    int b  = blockIdx.x * 256 + threadIdx.x;   // 0..65535
    int k4 = (b & 127) * 4;
    int n  = (b >> 7) & 63;
    int h  = b >> 13;
    const float* src = W + (size_t)h * 32768 + (size_t)k4 * 64 + n;
    __align__(8) __half hs[4];
    hs[0] = __float2half_rn(src[0]);
    hs[1] = __float2half_rn(src[64]);
    hs[2] = __float2half_rn(src[128]);
    hs[3] = __float2half_rn(src[192]);
    *(uint2*)(g_Wth + (size_t)h * 32768 + (size_t)n * 512 + k4) = *(uint2*)hs;
}

// ---------------------------------------------------------------------------
// Kernel 1: adjacency row scan -> CSR (deterministic ascending order)
// ---------------------------------------------------------------------------
__global__ __launch_bounds__(256) void scan_kernel(const float* __restrict__ adj)
{
    __shared__ int wsum[8];
    const int i   = blockIdx.x;
    const int tid = threadIdx.x;
    const int lane = tid & 31, wid = tid >> 5;

    const float4* row = (const float4*)(adj + (size_t)i * N_NODES) + tid * 4;
    unsigned bits = 0;
#pragma unroll
    for (int p = 0; p < 4; p++) {
        float4 v = row[p];
        if (v.x > 0.f) bits |= 1u << (p * 4 + 0);
        if (v.y > 0.f) bits |= 1u << (p * 4 + 1);
        if (v.z > 0.f) bits |= 1u << (p * 4 + 2);
        if (v.w > 0.f) bits |= 1u << (p * 4 + 3);
    }
    int cnt = __popc(bits);
    int incl = cnt;
#pragma unroll
    for (int o = 1; o < 32; o <<= 1) {
        int t = __shfl_up_sync(0xffffffffu, incl, o);
        if (lane >= o) incl += t;
    }
    if (lane == 31) wsum[wid] = incl;
    __syncthreads();
    int wbase = 0;
#pragma unroll
    for (int w = 0; w < 8; w++) if (w < wid) wbase += wsum[w];
    int pos = wbase + incl - cnt;
    if (tid == 0) {
        int t = 0;
#pragma unroll
        for (int w = 0; w < 8; w++) t += wsum[w];
        g_deg[i] = t;
    }
    int base = tid * 16;
    int* dst = g_nbr + (size_t)i * CAP;
    while (bits) {
        int b = __ffs(bits) - 1;
        bits &= bits - 1;
        dst[pos++] = base + b;
    }
}

// ---------------------------------------------------------------------------
// Kernel 2: fp16 2-term GEMM + fused s/d epilogue.
// Block: M=128 x N=64 (one head), BK=32, 256 threads.
// 8 warps: wm = warp>>1 (m32 = 2 x m16), wn = warp&1 (n32 = 4 x n8).
// cp.async double-buffered staging (pre-split gmem, no conversion in loop).
// Smem row stride 40 halfs (80 B) -> conflict-free frag loads + aligned cp.
// ---------------------------------------------------------------------------
#define NKB   16          // 512 / 32
#define LDH   40          // smem row stride in halfs
#define A_H   (128 * LDH) // halfs per A matrix (5120)
#define B_H   (64 * LDH)  // halfs per B matrix (2560)
#define BUF_H (2 * A_H + B_H)             // 12800 halfs per buffer
#define DYN_BYTES (2 * BUF_H * 2 + 512 + 2048)  // tiles + a_sm + sd scratch

__device__ __forceinline__ uint32_t smem_u32(const void* p) {
    uint32_t a;
    asm("{ .reg .u64 t; cvta.to.shared.u64 t, %1; cvt.u32.u64 %0, t; }"
        : "=r"(a) : "l"(p));
    return a;
}
__device__ __forceinline__ void cp16(uint32_t dst, const void* src) {
    asm volatile("cp.async.ca.shared.global [%0], [%1], 16;"
                 :: "r"(dst), "l"(src) : "memory");
}
__device__ __forceinline__ void mma_f16(float* d, uint32_t a0, uint32_t a1,
                                        uint32_t a2, uint32_t a3,
                                        uint32_t b0, uint32_t b1)
{
    asm volatile(
        "mma.sync.aligned.m16n8k16.row.col.f32.f16.f16.f32 "
        "{%0,%1,%2,%3}, {%4,%5,%6,%7}, {%8,%9}, {%0,%1,%2,%3};"
        : "+f"(d[0]), "+f"(d[1]), "+f"(d[2]), "+f"(d[3])
        : "r"(a0), "r"(a1), "r"(a2), "r"(a3), "r"(b0), "r"(b1));
}

__global__ __launch_bounds__(256) void gemm_f16(const float* __restrict__ a_g)
{
    extern __shared__ __align__(16) char sm[];
    __half* tiles = (__half*)sm;                        // 2 buffers
    float*  a_sm  = (float*)(sm + 2 * BUF_H * 2);       // 128 floats
    float*  sd_sm = (float*)(sm + 2 * BUF_H * 2 + 512); // [128][2][2]

    const int tid  = threadIdx.x;
    const int lane = tid & 31, warp = tid >> 5;
    const int h    = blockIdx.x;
    const int m0   = blockIdx.y * 128;
    const int wm   = warp >> 1, wn = warp & 1;
    const int gid  = lane >> 2, tig = lane & 3;

    const __half* xh  = g_xh + (size_t)m0 * F_IN;
    const __half* xl  = g_xl + (size_t)m0 * F_IN;
    const __half* wth = g_Wth + (size_t)h * 32768;

    if (tid < 128) a_sm[tid] = a_g[h * 128 + tid];

    const uint32_t tiles_u = smem_u32(tiles);

    // stage one k-block (id = p*256+tid, p<5): Ah, Al, Bh via 16B cp.async
    auto stage = [&](int buf, int k0) {
        uint32_t bu = tiles_u + buf * (BUF_H * 2);
#pragma unroll
        for (int p = 0; p < 5; p++) {
            int id = tid + p * 256;
            if (id < 512) {                       // A hi
                int r = id >> 2, seg = id & 3;
                cp16(bu + (r * LDH + seg * 8) * 2, xh + (size_t)r * F_IN + k0 + seg * 8);
            } else if (id < 1024) {               // A lo
                int q = id - 512, r = q >> 2, seg = q & 3;
                cp16(bu + (A_H + r * LDH + seg * 8) * 2, xl + (size_t)r * F_IN + k0 + seg * 8);
            } else {                              // B hi
                int q = id - 1024, r = q >> 2, seg = q & 3;
                cp16(bu + (2 * A_H + r * LDH + seg * 8) * 2, wth + (size_t)r * F_IN + k0 + seg * 8);
            }
        }
        asm volatile("cp.async.commit_group;" ::: "memory");
    };

    float acc[2][4][4];
#pragma unroll
    for (int mt = 0; mt < 2; mt++)
#pragma unroll
        for (int nt = 0; nt < 4; nt++)
#pragma unroll
            for (int r = 0; r < 4; r++) acc[mt][nt][r] = 0.f;

    stage(0, 0);

    for (int kb = 0; kb < NKB; kb++) {
        asm volatile("cp.async.wait_group 0;" ::: "memory");
        __syncthreads();
        if (kb + 1 < NKB) stage((kb + 1) & 1, (kb + 1) * 32);

        const __half* Ah = tiles + (kb & 1) * BUF_H;
        const __half* Al = Ah + A_H;
        const __half* Bh = Ah + 2 * A_H;

#pragma unroll
        for (int c = 0; c < 2; c++) {
            const int kb16 = c * 16 + 2 * tig;
            uint32_t bfr[4][2];
#pragma unroll
            for (int nt = 0; nt < 4; nt++) {
                const int col = wn * 32 + nt * 8 + gid;
                bfr[nt][0] = *(const uint32_t*)(Bh + col * LDH + kb16);
                bfr[nt][1] = *(const uint32_t*)(Bh + col * LDH + kb16 + 8);
            }
#pragma unroll
            for (int mt = 0; mt < 2; mt++) {
                const int r0 = wm * 32 + mt * 16 + gid;
                uint32_t ah0 = *(const uint32_t*)(Ah + r0 * LDH + kb16);
                uint32_t ah1 = *(const uint32_t*)(Ah + (r0 + 8) * LDH + kb16);
                uint32_t ah2 = *(const uint32_t*)(Ah + r0 * LDH + kb16 + 8);
                uint32_t ah3 = *(const uint32_t*)(Ah + (r0 + 8) * LDH + kb16 + 8);
                uint32_t al0 = *(const uint32_t*)(Al + r0 * LDH + kb16);
                uint32_t al1 = *(const uint32_t*)(Al + (r0 + 8) * LDH + kb16);
                uint32_t al2 = *(const uint32_t*)(Al + r0 * LDH + kb16 + 8);
                uint32_t al3 = *(const uint32_t*)(Al + (r0 + 8) * LDH + kb16 + 8);
#pragma unroll
                for (int nt = 0; nt < 4; nt++) {
                    mma_f16(acc[mt][nt], ah0, ah1, ah2, ah3, bfr[nt][0], bfr[nt][1]);
                    mma_f16(acc[mt][nt], al0, al1, al2, al3, bfr[nt][0], bfr[nt][1]);
                }
            }
        }
    }

    // ---- epilogue: write Wh + fused s/d ----
    float sp[2][2], dp[2][2];
#pragma unroll
    for (int mt = 0; mt < 2; mt++) {
        sp[mt][0] = sp[mt][1] = dp[mt][0] = dp[mt][1] = 0.f;
        const int gr = m0 + wm * 32 + mt * 16 + gid;
#pragma unroll
        for (int nt = 0; nt < 4; nt++) {
            const int coll = wn * 32 + nt * 8 + 2 * tig;   // local col 0..63
            const int col  = h * HID + coll;
            *(float2*)(g_Wh + (size_t)gr * NCOLS + col)       = make_float2(acc[mt][nt][0], acc[mt][nt][1]);
            *(float2*)(g_Wh + (size_t)(gr + 8) * NCOLS + col) = make_float2(acc[mt][nt][2], acc[mt][nt][3]);
#pragma unroll
            for (int cc = 0; cc < 2; cc++) {
                float as = a_sm[coll + cc], ad = a_sm[64 + coll + cc];
                sp[mt][0] = fmaf(acc[mt][nt][cc],     as, sp[mt][0]);
                sp[mt][1] = fmaf(acc[mt][nt][2 + cc], as, sp[mt][1]);
                dp[mt][0] = fmaf(acc[mt][nt][cc],     ad, dp[mt][0]);
                dp[mt][1] = fmaf(acc[mt][nt][2 + cc], ad, dp[mt][1]);
            }
        }
    }
    // reduce over tig (4 threads share each row-half)
#pragma unroll
    for (int o = 1; o < 4; o <<= 1) {
#pragma unroll
        for (int mt = 0; mt < 2; mt++) {
#pragma unroll
            for (int hf = 0; hf < 2; hf++) {
                sp[mt][hf] += __shfl_xor_sync(0xffffffffu, sp[mt][hf], o);
                dp[mt][hf] += __shfl_xor_sync(0xffffffffu, dp[mt][hf], o);
            }
        }
    }
    if (tig == 0) {
#pragma unroll
        for (int mt = 0; mt < 2; mt++)
#pragma unroll
            for (int hf = 0; hf < 2; hf++) {
                int row = wm * 32 + mt * 16 + gid + hf * 8;   // 0..127
                sd_sm[row * 4 + wn * 2 + 0] = sp[mt][hf];
                sd_sm[row * 4 + wn * 2 + 1] = dp[mt][hf];
            }
    }
    __syncthreads();
    if (tid < 128) {
        float s = sd_sm[tid * 4 + 0] + sd_sm[tid * 4 + 2];
        float d = sd_sm[tid * 4 + 1] + sd_sm[tid * 4 + 3];
        int gr = m0 + tid;
        g_SAB[gr * 8 + h] = make_float4(s, expf(s), expf(0.2f * s), 0.f);
        g_DJE[gr * 8 + h] = make_float4(d, expf(d), expf(0.2f * d), 0.f);
    }
}

// ---------------------------------------------------------------------------
// Kernel 3: aggregation. 1 block/row, 128 threads, float4 gathers from L2.
// ---------------------------------------------------------------------------
__global__ __launch_bounds__(128) void attn_kernel(float* __restrict__ out)
{
    __shared__ int    s_list[CAP];
    __shared__ float  s_w[CAP * 8];
    __shared__ float4 s_sab[8];

    const int i   = blockIdx.x;
    const int tid = threadIdx.x;
    const int h   = tid >> 4;

    const int nn = g_deg[i];
    if (tid < 8) s_sab[tid] = g_SAB[i * 8 + tid];
    for (int p = tid; p < nn; p += 128) s_list[p] = g_nbr[(size_t)i * CAP + p];
    __syncthreads();

    for (int idx = tid; idx < nn * 8; idx += 128) {
        int q = idx >> 3, hh = idx & 7;
        int j = s_list[q];
        float4 dje = g_DJE[j * 8 + hh];
        float4 sab = s_sab[hh];
        float t = sab.x + dje.x;
        s_w[idx] = (t > 0.f) ? sab.y * dje.y : sab.z * dje.z;
    }
    __syncthreads();

    const float4* wh4 = (const float4*)g_Wh;
    const float*  wp  = s_w + h;
    float4 acc = make_float4(0.f, 0.f, 0.f, 0.f);
    float  den = 0.f;

#pragma unroll 4
    for (int q = 0; q < nn; q++) {
        float w = wp[q * 8];
        int   j = s_list[q];
        float4 v = __ldg(&wh4[(size_t)j * 128 + tid]);
        acc.x = fmaf(w, v.x, acc.x);
        acc.y = fmaf(w, v.y, acc.y);
        acc.z = fmaf(w, v.z, acc.z);
        acc.w = fmaf(w, v.w, acc.w);
        den += w;
    }

    float inv = 1.f / den;
    float4 r = make_float4(acc.x * inv, acc.y * inv, acc.z * inv, acc.w * inv);
    r.x = (r.x > 0.f) ? r.x : (expf(r.x) - 1.f);
    r.y = (r.y > 0.f) ? r.y : (expf(r.y) - 1.f);
    r.z = (r.z > 0.f) ? r.z : (expf(r.z) - 1.f);
    r.w = (r.w > 0.f) ? r.w : (expf(r.w) - 1.f);
    *(float4*)(out + (size_t)i * NCOLS + tid * 4) = r;
}

// ---------------------------------------------------------------------------
extern "C" void kernel_launch(void* const* d_in, const int* in_sizes, int n_in,
                              void* d_out, int out_size)
{
    const float* x   = (const float*)d_in[0];   // [4096, 512]
    const float* adj = (const float*)d_in[1];   // [4096, 4096]
    const float* W   = (const float*)d_in[2];   // [8, 512, 64]
    const float* a   = (const float*)d_in[3];   // [8, 128]
    float* out = (float*)d_out;                 // [4096, 512]

    static bool attr_set = false;
    if (!attr_set) {
        cudaFuncSetAttribute(gemm_f16, cudaFuncAttributeMaxDynamicSharedMemorySize, DYN_BYTES);
        attr_set = true;
    }

    prep_x<<<1024, 256>>>(x);
    prep_w<<<256, 256>>>(W);
    scan_kernel<<<N_NODES, 256>>>(adj);
    gemm_f16<<<dim3(NHEADS, N_NODES / 128), 256, DYN_BYTES>>>(a);
    attn_kernel<<<N_NODES, 128>>>(out);
}